// round 10
// baseline (speedup 1.0000x reference)
#include <cuda_runtime.h>
#include <math.h>

#define DD 1024
#define HH 8
#define DHH 128
#define FF 4096
#define VV 16384
#define ENCN 438
#define PASTN 447
#define TKN 448
#define LL 8
#define ATT_SCALE 0.08838834764831845f   // 1/sqrt(128)

struct Scratch {
    float qkv[3 * DD];     // zeroed per layer (atomic accum)
    float qc[DD];          // zeroed
    float ffnpre[FF];      // zeroed
    float oc[DD];          // zeroed
    float os[DD];          // zeroed
    float x[DD];           // residual stream (persists)
    float xf[DD];          // final LN output
    float ss[HH * TKN];    // self-attn scores
    float cs[HH * TKN];    // cross-attn scores (438 used)
    float t[HH * DD];      // t[h,j] = q_c[h] . wk_c[j, h*128:+128]
    float u[HH * DD];      // u[h,j] = sum_e a[h,e] enc[e,j]
};
__device__ Scratch g_s;
#define ZERO_FLOATS (3 * DD + DD + FF + DD + DD)   // 10240 floats at struct start

// ---------------- reductions ----------------
__device__ __forceinline__ float warp_sum(float v) {
#pragma unroll
    for (int o = 16; o; o >>= 1) v += __shfl_xor_sync(0xffffffffu, v, o);
    return v;
}
__device__ __forceinline__ float warp_max(float v) {
#pragma unroll
    for (int o = 16; o; o >>= 1) v = fmaxf(v, __shfl_xor_sync(0xffffffffu, v, o));
    return v;
}
// block-wide reduce; all threads must call; works for blockDim 128/256
__device__ __forceinline__ float blk_reduce(float v, bool do_max) {
    __shared__ float sm[8];
    int w = threadIdx.x >> 5, ln = threadIdx.x & 31, nw = blockDim.x >> 5;
    v = do_max ? warp_max(v) : warp_sum(v);
    __syncthreads();
    if (ln == 0) sm[w] = v;
    __syncthreads();
    if (threadIdx.x == 0) {
        float r = sm[0];
        for (int i = 1; i < nw; i++) r = do_max ? fmaxf(r, sm[i]) : (r + sm[i]);
        sm[0] = r;
    }
    __syncthreads();
    float r = sm[0];
    __syncthreads();
    return r;
}

// LayerNorm of g_s.x (1024) into out (smem or gmem). Requires blockDim == 256.
__device__ __forceinline__ void blk_layernorm(const float* __restrict__ x,
                                              const float* __restrict__ g,
                                              const float* __restrict__ b,
                                              float* out) {
    int tid = threadIdx.x;
    float4 xv = __ldg((const float4*)x + tid);
    float s  = xv.x + xv.y + xv.z + xv.w;
    float sq = xv.x * xv.x + xv.y * xv.y + xv.z * xv.z + xv.w * xv.w;
    float S  = blk_reduce(s, false);
    float SQ = blk_reduce(sq, false);
    float mean = S * (1.0f / DD);
    float var  = SQ * (1.0f / DD) - mean * mean;
    float inv  = rsqrtf(var + 1e-5f);
    float4 gv = __ldg((const float4*)g + tid);
    float4 bv = __ldg((const float4*)b + tid);
    float4 o;
    o.x = (xv.x - mean) * inv * gv.x + bv.x;
    o.y = (xv.y - mean) * inv * gv.y + bv.y;
    o.z = (xv.z - mean) * inv * gv.z + bv.z;
    o.w = (xv.w - mean) * inv * gv.w + bv.w;
    ((float4*)out)[tid] = o;
    __syncthreads();
}

// GEMV tile core: 256 threads = 8 i-groups x 32 o-lanes (float4 per lane).
// out[obase + 0..127] += xs[0..R-1] . W[ibase .. ibase+R-1, obase .. +127]
__device__ __forceinline__ void gemv_core(const float* __restrict__ W, int ld,
                                          const float* __restrict__ xs,
                                          int ibase, int R, int obase,
                                          float* __restrict__ out) {
    int ol = threadIdx.x & 31;
    int ig = threadIdx.x >> 5;
    int o  = obase + ol * 4;
    int rpg = R >> 3;
    float4 acc = make_float4(0.f, 0.f, 0.f, 0.f);
    const float* Wb = W + (size_t)(ibase + ig * rpg) * ld + o;
    const float* xb = xs + ig * rpg;
#pragma unroll 8
    for (int r = 0; r < rpg; r++) {
        float xi = xb[r];
        float4 w = __ldg((const float4*)(Wb + (size_t)r * ld));
        acc.x = fmaf(xi, w.x, acc.x);
        acc.y = fmaf(xi, w.y, acc.y);
        acc.z = fmaf(xi, w.z, acc.z);
        acc.w = fmaf(xi, w.w, acc.w);
    }
    __shared__ float4 red[8][32];
    red[ig][ol] = acc;
    __syncthreads();
    if (ig == 0) {
        float4 tv = red[0][ol];
#pragma unroll
        for (int k2 = 1; k2 < 8; k2++) {
            float4 uv = red[k2][ol];
            tv.x += uv.x; tv.y += uv.y; tv.z += uv.z; tv.w += uv.w;
        }
        atomicAdd(&out[o + 0], tv.x);
        atomicAdd(&out[o + 1], tv.y);
        atomicAdd(&out[o + 2], tv.z);
        atomicAdd(&out[o + 3], tv.w);
    }
}

// ---------------- kernels ----------------
__global__ void k_init(const int* __restrict__ ids, const int* __restrict__ plen,
                       const float* __restrict__ emb, const float* __restrict__ pos) {
    int tid = threadIdx.x;
    int id = ids[0];
    int pl = plen[0];
    float4 e = __ldg((const float4*)(emb + (size_t)id * DD) + tid);
    float4 p = __ldg((const float4*)(pos + (size_t)pl * DD) + tid);
    float4 o;
    o.x = e.x + p.x; o.y = e.y + p.y; o.z = e.z + p.z; o.w = e.w + p.w;
    ((float4*)g_s.x)[tid] = o;
}

// LN1 + q/k/v projections. grid 192: m(3) x otile(8) x isplit(8)
__global__ __launch_bounds__(256) void k_qkv(const float* __restrict__ wq,
                                             const float* __restrict__ wk,
                                             const float* __restrict__ wv,
                                             const float* __restrict__ lg,
                                             const float* __restrict__ lb, int l) {
    __shared__ float hln[DD];
    int m = blockIdx.x >> 6;
    int r2 = blockIdx.x & 63;
    int otile = r2 >> 3;
    int isplit = r2 & 7;
    blk_layernorm(g_s.x, lg + l * DD, lb + l * DD, hln);
    const float* W = (m == 0 ? wq : (m == 1 ? wk : wv)) + (size_t)l * DD * DD;
    gemv_core(W, DD, hln + isplit * 128, isplit * 128, 128, otile * 128,
              g_s.qkv + m * DD);
}

// self-attn scores: one warp per (h,t)
__global__ __launch_bounds__(256) void k_sscore(const float* __restrict__ past_k, int l) {
    int w = threadIdx.x >> 5, ln = threadIdx.x & 31;
    int task = blockIdx.x * 8 + w;
    int h = task / TKN, t = task % TKN;
    const float* kr = (t < PASTN)
        ? past_k + (((size_t)l * HH + h) * PASTN + t) * DHH
        : g_s.qkv + DD + h * DHH;
    float4 k4 = __ldg((const float4*)kr + ln);
    float4 q4 = __ldg((const float4*)(g_s.qkv + h * DHH) + ln);
    float d = k4.x * q4.x + k4.y * q4.y + k4.z * q4.z + k4.w * q4.w;
    d = warp_sum(d);
    if (ln == 0) g_s.ss[h * TKN + t] = d * ATT_SCALE;
}

// softmax (redundant stats per block) + A*V partial. grid 56 = h(8) x chunk(7)
__global__ __launch_bounds__(128) void k_sav(const float* __restrict__ past_v, int l) {
    int h = blockIdx.x / 7, ch = blockIdx.x % 7;
    int tid = threadIdx.x;
    const float* ssr = g_s.ss + h * TKN;
    float mxl = -1e30f;
    for (int t = tid; t < TKN; t += 128) mxl = fmaxf(mxl, ssr[t]);
    float mx = blk_reduce(mxl, true);
    float sl = 0.f;
    for (int t = tid; t < TKN; t += 128) sl += expf(ssr[t] - mx);
    float S = blk_reduce(sl, false);
    float inv = 1.f / S;
    float acc = 0.f;
    int t0 = ch * 64;
    for (int tt = t0; tt < t0 + 64; tt++) {
        float wgt = expf(ssr[tt] - mx);
        const float* vr = (tt < PASTN)
            ? past_v + (((size_t)l * HH + h) * PASTN + tt) * DHH
            : g_s.qkv + 2 * DD + h * DHH;
        acc = fmaf(wgt, __ldg(vr + tid), acc);
    }
    atomicAdd(&g_s.os[h * DHH + tid], acc * inv);
}

// plain GEMV (Din=1024, Dout=1024), grid 128 = otile(8) x isplit(16)
// mode 0: os @ W -> +x ; mode 1: oc @ W -> +x ; mode 2: u[head] @ W -> oc
__global__ __launch_bounds__(256) void k_gemv_plain(const float* __restrict__ W,
                                                    int mode, int l) {
    __shared__ float xs[64];
    int otile = blockIdx.x >> 4;
    int isplit = blockIdx.x & 15;
    const float* gv = (mode == 0) ? g_s.os : ((mode == 1) ? g_s.oc : g_s.u + otile * DD);
    float* out = (mode == 2) ? g_s.oc : g_s.x;
    int ibase = isplit * 64;
    if (threadIdx.x < 64) xs[threadIdx.x] = __ldg(gv + ibase + threadIdx.x);
    __syncthreads();
    gemv_core(W + (size_t)l * DD * DD, DD, xs, ibase, 64, otile * 128, out);
}

// LN + GEMV; mode 0: -> qc (ld=1024, nsplit=16); mode 1: -> ffnpre (ld=4096, nsplit=4)
__global__ __launch_bounds__(256) void k_ln_gemv(const float* __restrict__ W,
                                                 const float* __restrict__ lg,
                                                 const float* __restrict__ lb,
                                                 int ld, int nsplit, int mode, int l) {
    __shared__ float hln[DD];
    int otile = blockIdx.x / nsplit;
    int isplit = blockIdx.x % nsplit;
    int R = DD / nsplit;
    blk_layernorm(g_s.x, lg + l * DD, lb + l * DD, hln);
    float* out = (mode == 0) ? g_s.qc : g_s.ffnpre;
    size_t woff = (mode == 0) ? (size_t)l * DD * DD : (size_t)l * DD * FF;
    gemv_core(W + woff, ld, hln + isplit * R, isplit * R, R, otile * 128, out);
}

// t[h,j] = q_c[h] . wk_c[j, h*128:+128]; one warp per j-row, 8 heads per warp
__global__ __launch_bounds__(256) void k_t(const float* __restrict__ wk_c, int l) {
    int w = threadIdx.x >> 5, ln = threadIdx.x & 31;
    int j = blockIdx.x * 8 + w;
    const float* row = wk_c + (size_t)l * DD * DD + (size_t)j * DD;
#pragma unroll
    for (int h = 0; h < HH; h++) {
        float4 wv4 = __ldg((const float4*)(row + h * DHH) + ln);
        float4 q4  = __ldg((const float4*)(g_s.qc + h * DHH) + ln);
        float d = wv4.x * q4.x + wv4.y * q4.y + wv4.z * q4.z + wv4.w * q4.w;
        d = warp_sum(d);
        if (ln == 0) g_s.t[h * DD + j] = d;
    }
}

// cross scores: cs[h,e] = scale * enc[e,:] . t[h,:] ; one block per e
__global__ __launch_bounds__(256) void k_cscore(const float* __restrict__ enc) {
    int e = blockIdx.x;
    int tid = threadIdx.x;
    float4 ev = __ldg((const float4*)(enc + (size_t)e * DD) + tid);
    float acc[HH];
#pragma unroll
    for (int h = 0; h < HH; h++) {
        float4 tv = __ldg((const float4*)(g_s.t + h * DD) + tid);
        acc[h] = ev.x * tv.x + ev.y * tv.y + ev.z * tv.z + ev.w * tv.w;
    }
#pragma unroll
    for (int h = 0; h < HH; h++) {
        float s = blk_reduce(acc[h], false);
        if (tid == 0) g_s.cs[h * TKN + e] = s * ATT_SCALE;
    }
}

// u[h,j] = softmax(cs[h,:]) . enc[:,j] ; grid 32 = h(8) x jchunk(4)
__global__ __launch_bounds__(256) void k_u(const float* __restrict__ enc) {
    __shared__ float a[ENCN];
    int h = blockIdx.x >> 2, jc = blockIdx.x & 3;
    int tid = threadIdx.x;
    const float* csr = g_s.cs + h * TKN;
    float mxl = -1e30f;
    for (int e = tid; e < ENCN; e += 256) mxl = fmaxf(mxl, csr[e]);
    float mx = blk_reduce(mxl, true);
    float sl = 0.f;
    for (int e = tid; e < ENCN; e += 256) {
        float v = expf(csr[e] - mx);
        a[e] = v;
        sl += v;
    }
    float S = blk_reduce(sl, false);
    float inv = 1.f / S;
    int j = jc * 256 + tid;
    float acc = 0.f;
#pragma unroll 4
    for (int e = 0; e < ENCN; e++)
        acc = fmaf(a[e], __ldg(enc + (size_t)e * DD + j), acc);
    g_s.u[h * DD + j] = acc * inv;
}

// FFN second matmul with gelu(tanh) applied to the staged input slice
__global__ __launch_bounds__(256) void k_ffn2(const float* __restrict__ w2, int l) {
    __shared__ float xs[256];
    int otile = blockIdx.x >> 4;
    int isplit = blockIdx.x & 15;
    int ibase = isplit * 256;
    float v = g_s.ffnpre[ibase + threadIdx.x];
    float v3 = v * v * v;
    xs[threadIdx.x] = 0.5f * v * (1.f + tanhf(0.7978845608028654f * (v + 0.044715f * v3)));
    __syncthreads();
    gemv_core(w2 + (size_t)l * FF * DD, DD, xs, ibase, 256, otile * 128, g_s.x);
}

__global__ __launch_bounds__(256) void k_lnf(const float* __restrict__ lg,
                                             const float* __restrict__ lb) {
    blk_layernorm(g_s.x, lg, lb, g_s.xf);
}

// logits[v] = xf . emb[v,:] ; one warp per 4 rows (row-major dot, coalesced)
__global__ __launch_bounds__(256) void k_logits(const float* __restrict__ emb,
                                                float* __restrict__ out) {
    int w = threadIdx.x >> 5, ln = threadIdx.x & 31;
    int vb = (blockIdx.x * 8 + w) * 4;
    float4 xr[8];
#pragma unroll
    for (int kk = 0; kk < 8; kk++)
        xr[kk] = __ldg((const float4*)g_s.xf + kk * 32 + ln);
#pragma unroll
    for (int r = 0; r < 4; r++) {
        const float4* er = (const float4*)(emb + (size_t)(vb + r) * DD);
        float acc = 0.f;
#pragma unroll
        for (int kk = 0; kk < 8; kk++) {
            float4 e4 = __ldg(er + kk * 32 + ln);
            float4 x4 = xr[kk];
            acc += e4.x * x4.x + e4.y * x4.y + e4.z * x4.z + e4.w * x4.w;
        }
        acc = warp_sum(acc);
        if (ln == 0) out[vb + r] = acc;
    }
}

// ---------------- launcher ----------------
extern "C" void kernel_launch(void* const* d_in, const int* in_sizes, int n_in,
                              void* d_out, int out_size) {
    const int*   input_ids = (const int*)d_in[0];
    const float* enc    = (const float*)d_in[1];
    const float* past_k = (const float*)d_in[2];
    const float* past_v = (const float*)d_in[3];
    const float* emb    = (const float*)d_in[4];
    const float* pos    = (const float*)d_in[5];
    const float* ln1_g  = (const float*)d_in[6];
    const float* ln1_b  = (const float*)d_in[7];
    const float* wq_s   = (const float*)d_in[8];
    const float* wk_s   = (const float*)d_in[9];
    const float* wv_s   = (const float*)d_in[10];
    const float* wo_s   = (const float*)d_in[11];
    const float* ln2_g  = (const float*)d_in[12];
    const float* ln2_b  = (const float*)d_in[13];
    const float* wq_c   = (const float*)d_in[14];
    const float* wk_c   = (const float*)d_in[15];
    const float* wv_c   = (const float*)d_in[16];
    const float* wo_c   = (const float*)d_in[17];
    const float* ln3_g  = (const float*)d_in[18];
    const float* ln3_b  = (const float*)d_in[19];
    const float* w1     = (const float*)d_in[20];
    const float* w2     = (const float*)d_in[21];
    const float* lnf_g  = (const float*)d_in[22];
    const float* lnf_b  = (const float*)d_in[23];
    const int*   plen   = (const int*)d_in[24];
    float* out = (float*)d_out;

    void* sp = nullptr;
    cudaGetSymbolAddress(&sp, g_s);

    k_init<<<1, 256>>>(input_ids, plen, emb, pos);
    for (int l = 0; l < LL; l++) {
        cudaMemsetAsync(sp, 0, ZERO_FLOATS * sizeof(float));
        k_qkv<<<192, 256>>>(wq_s, wk_s, wv_s, ln1_g, ln1_b, l);
        k_sscore<<<448, 256>>>(past_k, l);
        k_sav<<<56, 128>>>(past_v, l);
        k_gemv_plain<<<128, 256>>>(wo_s, 0, l);            // x += o_s @ wo_s
        k_ln_gemv<<<128, 256>>>(wq_c, ln2_g, ln2_b, DD, 16, 0, l);  // qc
        k_t<<<128, 256>>>(wk_c, l);
        k_cscore<<<438, 256>>>(enc);
        k_u<<<32, 256>>>(enc);
        k_gemv_plain<<<128, 256>>>(wv_c, 2, l);            // oc = u @ wv_c (per-head)
        k_gemv_plain<<<128, 256>>>(wo_c, 1, l);            // x += o_c @ wo_c
        k_ln_gemv<<<128, 256>>>(w1, ln3_g, ln3_b, FF, 4, 1, l);     // ffnpre
        k_ffn2<<<128, 256>>>(w2, l);                        // x += gelu(ffnpre) @ w2
    }
    k_lnf<<<1, 256>>>(lnf_g, lnf_b);
    k_logits<<<512, 256>>>(emb, out);
}

// round 11
// speedup vs baseline: 1.5804x; 1.5804x over previous
#include <cuda_runtime.h>
#include <math.h>

#define DD 1024
#define HH 8
#define DHH 128
#define FF 4096
#define VV 16384
#define ENCN 438
#define PASTN 447
#define TKN 448
#define LL 8
#define ATT_SCALE 0.08838834764831845f   // 1/sqrt(128)

struct Scratch {
    float qkv[3 * DD];     // zeroed per layer (atomic accum)
    float qc[DD];          // zeroed
    float ffnpre[FF];      // zeroed
    float oc[DD];          // zeroed
    float os[DD];          // zeroed
    float u[HH * DD];      // zeroed (atomic accum now)
    float x[DD];           // residual stream (persists)
    float ss[HH * TKN];    // self-attn scores
    float cs[HH * TKN];    // cross-attn scores (438 used)
    float t[HH * DD];      // t[h,j] = q_c[h] . wk_c[j, h*128:+128]
};
__device__ Scratch g_s;
#define ZERO_FLOATS (3 * DD + DD + FF + DD + DD + HH * DD)   // through u

// ---------------- reductions ----------------
__device__ __forceinline__ float warp_sum(float v) {
#pragma unroll
    for (int o = 16; o; o >>= 1) v += __shfl_xor_sync(0xffffffffu, v, o);
    return v;
}
__device__ __forceinline__ float warp_max(float v) {
#pragma unroll
    for (int o = 16; o; o >>= 1) v = fmaxf(v, __shfl_xor_sync(0xffffffffu, v, o));
    return v;
}
__device__ __forceinline__ float blk_reduce(float v, bool do_max) {
    __shared__ float sm[8];
    int w = threadIdx.x >> 5, ln = threadIdx.x & 31, nw = blockDim.x >> 5;
    v = do_max ? warp_max(v) : warp_sum(v);
    __syncthreads();
    if (ln == 0) sm[w] = v;
    __syncthreads();
    if (threadIdx.x == 0) {
        float r = sm[0];
        for (int i = 1; i < nw; i++) r = do_max ? fmaxf(r, sm[i]) : (r + sm[i]);
        sm[0] = r;
    }
    __syncthreads();
    float r = sm[0];
    __syncthreads();
    return r;
}

// LayerNorm of x (1024) into out. Requires blockDim == 256.
__device__ __forceinline__ void blk_layernorm(const float* __restrict__ x,
                                              const float* __restrict__ g,
                                              const float* __restrict__ b,
                                              float* out) {
    int tid = threadIdx.x;
    float4 xv = __ldg((const float4*)x + tid);
    float s  = xv.x + xv.y + xv.z + xv.w;
    float sq = xv.x * xv.x + xv.y * xv.y + xv.z * xv.z + xv.w * xv.w;
    float S  = blk_reduce(s, false);
    float SQ = blk_reduce(sq, false);
    float mean = S * (1.0f / DD);
    float var  = SQ * (1.0f / DD) - mean * mean;
    float inv  = rsqrtf(var + 1e-5f);
    float4 gv = __ldg((const float4*)g + tid);
    float4 bv = __ldg((const float4*)b + tid);
    float4 o;
    o.x = (xv.x - mean) * inv * gv.x + bv.x;
    o.y = (xv.y - mean) * inv * gv.y + bv.y;
    o.z = (xv.z - mean) * inv * gv.z + bv.z;
    o.w = (xv.w - mean) * inv * gv.w + bv.w;
    ((float4*)out)[tid] = o;
    __syncthreads();
}

// GEMV tile core: 256 threads = 8 i-groups x 32 o-lanes (float4 per lane).
// out[obase + 0..127] += xs[0..R-1] . W[ibase .. ibase+R-1, obase .. +127]
// R must be a multiple of 8.
__device__ __forceinline__ void gemv_core(const float* __restrict__ W, int ld,
                                          const float* __restrict__ xs,
                                          int ibase, int R, int obase,
                                          float* __restrict__ out) {
    int ol = threadIdx.x & 31;
    int ig = threadIdx.x >> 5;
    int o  = obase + ol * 4;
    int rpg = R >> 3;
    float4 acc = make_float4(0.f, 0.f, 0.f, 0.f);
    const float* Wb = W + (size_t)(ibase + ig * rpg) * ld + o;
    const float* xb = xs + ig * rpg;
#pragma unroll 8
    for (int r = 0; r < rpg; r++) {
        float xi = xb[r];
        float4 w = __ldg((const float4*)(Wb + (size_t)r * ld));
        acc.x = fmaf(xi, w.x, acc.x);
        acc.y = fmaf(xi, w.y, acc.y);
        acc.z = fmaf(xi, w.z, acc.z);
        acc.w = fmaf(xi, w.w, acc.w);
    }
    __shared__ float4 red[8][32];
    red[ig][ol] = acc;
    __syncthreads();
    if (ig == 0) {
        float4 tv = red[0][ol];
#pragma unroll
        for (int k2 = 1; k2 < 8; k2++) {
            float4 uv = red[k2][ol];
            tv.x += uv.x; tv.y += uv.y; tv.z += uv.z; tv.w += uv.w;
        }
        atomicAdd(&out[o + 0], tv.x);
        atomicAdd(&out[o + 1], tv.y);
        atomicAdd(&out[o + 2], tv.z);
        atomicAdd(&out[o + 3], tv.w);
    }
}

// ---------------- kernels ----------------
__global__ void k_init(const int* __restrict__ ids, const int* __restrict__ plen,
                       const float* __restrict__ emb, const float* __restrict__ pos) {
    int tid = threadIdx.x;
    int id = ids[0];
    int pl = plen[0];
    float4 e = __ldg((const float4*)(emb + (size_t)id * DD) + tid);
    float4 p = __ldg((const float4*)(pos + (size_t)pl * DD) + tid);
    float4 o;
    o.x = e.x + p.x; o.y = e.y + p.y; o.z = e.z + p.z; o.w = e.w + p.w;
    ((float4*)g_s.x)[tid] = o;
}

// LN1 + q/k/v projections. grid 384: m(3) x otile(8) x isplit(16)
__global__ __launch_bounds__(256) void k_qkv(const float* __restrict__ wq,
                                             const float* __restrict__ wk,
                                             const float* __restrict__ wv,
                                             const float* __restrict__ lg,
                                             const float* __restrict__ lb, int l) {
    __shared__ float hln[DD];
    int m = blockIdx.x >> 7;
    int r2 = blockIdx.x & 127;
    int otile = r2 >> 4;
    int isplit = r2 & 15;
    blk_layernorm(g_s.x, lg + l * DD, lb + l * DD, hln);
    const float* W = (m == 0 ? wq : (m == 1 ? wk : wv)) + (size_t)l * DD * DD;
    gemv_core(W, DD, hln + isplit * 64, isplit * 64, 64, otile * 128,
              g_s.qkv + m * DD);
}

// self-attn scores: one warp per (h,t)
__global__ __launch_bounds__(256) void k_sscore(const float* __restrict__ past_k, int l) {
    int w = threadIdx.x >> 5, ln = threadIdx.x & 31;
    int task = blockIdx.x * 8 + w;
    int h = task / TKN, t = task % TKN;
    const float* kr = (t < PASTN)
        ? past_k + (((size_t)l * HH + h) * PASTN + t) * DHH
        : g_s.qkv + DD + h * DHH;
    float4 k4 = __ldg((const float4*)kr + ln);
    float4 q4 = __ldg((const float4*)(g_s.qkv + h * DHH) + ln);
    float d = k4.x * q4.x + k4.y * q4.y + k4.z * q4.z + k4.w * q4.w;
    d = warp_sum(d);
    if (ln == 0) g_s.ss[h * TKN + t] = d * ATT_SCALE;
}

// softmax (redundant stats per block) + A*V partial.
// grid 224 = h(8) x chunk(28, 16 tokens each), block=128 (one thread per dim)
__global__ __launch_bounds__(128) void k_sav(const float* __restrict__ past_v, int l) {
    int h = blockIdx.x / 28, ch = blockIdx.x % 28;
    int tid = threadIdx.x;
    const float* ssr = g_s.ss + h * TKN;
    float mxl = -1e30f;
    for (int t = tid; t < TKN; t += 128) mxl = fmaxf(mxl, ssr[t]);
    float mx = blk_reduce(mxl, true);
    float sl = 0.f;
    for (int t = tid; t < TKN; t += 128) sl += expf(ssr[t] - mx);
    float S = blk_reduce(sl, false);
    float inv = 1.f / S;
    float acc = 0.f;
    int t0 = ch * 16;
#pragma unroll
    for (int tt = t0; tt < t0 + 16; tt++) {
        float wgt = expf(ssr[tt] - mx);
        const float* vr = (tt < PASTN)
            ? past_v + (((size_t)l * HH + h) * PASTN + tt) * DHH
            : g_s.qkv + 2 * DD + h * DHH;
        acc = fmaf(wgt, __ldg(vr + tid), acc);
    }
    atomicAdd(&g_s.os[h * DHH + tid], acc * inv);
}

// plain GEMV (Din=1024, Dout=1024), grid 256 = otile(8) x isplit(32)
// mode 0: os @ W -> +x ; mode 1: oc @ W -> +x ; mode 2: u[head] @ W -> oc
__global__ __launch_bounds__(256) void k_gemv_plain(const float* __restrict__ W,
                                                    int mode, int l) {
    __shared__ float xs[32];
    int otile = blockIdx.x >> 5;
    int isplit = blockIdx.x & 31;
    const float* gv = (mode == 0) ? g_s.os : ((mode == 1) ? g_s.oc : g_s.u + otile * DD);
    float* out = (mode == 2) ? g_s.oc : g_s.x;
    int ibase = isplit * 32;
    if (threadIdx.x < 32) xs[threadIdx.x] = __ldg(gv + ibase + threadIdx.x);
    __syncthreads();
    gemv_core(W + (size_t)l * DD * DD, DD, xs, ibase, 32, otile * 128, out);
}

// LN + GEMV; mode 0: -> qc (ld=1024, otile 8, nsplit=16); mode 1: -> ffnpre (ld=4096, otile 32, nsplit=8)
__global__ __launch_bounds__(256) void k_ln_gemv(const float* __restrict__ W,
                                                 const float* __restrict__ lg,
                                                 const float* __restrict__ lb,
                                                 int ld, int nsplit, int mode, int l) {
    __shared__ float hln[DD];
    int otile = blockIdx.x / nsplit;
    int isplit = blockIdx.x % nsplit;
    int R = DD / nsplit;
    blk_layernorm(g_s.x, lg + l * DD, lb + l * DD, hln);
    float* out = (mode == 0) ? g_s.qc : g_s.ffnpre;
    size_t woff = (mode == 0) ? (size_t)l * DD * DD : (size_t)l * DD * FF;
    gemv_core(W + woff, ld, hln + isplit * R, isplit * R, R, otile * 128, out);
}

// t[h,j] = q_c[h] . wk_c[j, h*128:+128]; one warp per j-row, 8 heads per warp
__global__ __launch_bounds__(256) void k_t(const float* __restrict__ wk_c, int l) {
    int w = threadIdx.x >> 5, ln = threadIdx.x & 31;
    int j = blockIdx.x * 8 + w;
    const float* row = wk_c + (size_t)l * DD * DD + (size_t)j * DD;
#pragma unroll
    for (int h = 0; h < HH; h++) {
        float4 wv4 = __ldg((const float4*)(row + h * DHH) + ln);
        float4 q4  = __ldg((const float4*)(g_s.qc + h * DHH) + ln);
        float d = wv4.x * q4.x + wv4.y * q4.y + wv4.z * q4.z + wv4.w * q4.w;
        d = warp_sum(d);
        if (ln == 0) g_s.t[h * DD + j] = d;
    }
}

// cross scores: cs[h,e] = scale * enc[e,:] . t[h,:] ; one block per e
__global__ __launch_bounds__(256) void k_cscore(const float* __restrict__ enc) {
    int e = blockIdx.x;
    int tid = threadIdx.x;
    float4 ev = __ldg((const float4*)(enc + (size_t)e * DD) + tid);
    float acc[HH];
#pragma unroll
    for (int h = 0; h < HH; h++) {
        float4 tv = __ldg((const float4*)(g_s.t + h * DD) + tid);
        acc[h] = ev.x * tv.x + ev.y * tv.y + ev.z * tv.z + ev.w * tv.w;
    }
#pragma unroll
    for (int h = 0; h < HH; h++) {
        float s = blk_reduce(acc[h], false);
        if (tid == 0) g_s.cs[h * TKN + e] = s * ATT_SCALE;
    }
}

// u[h,j] += softmax(cs[h,:])[echunk] . enc[echunk,j]
// grid 128 = h(8) x jchunk(4) x echunk(4); redundant stats per block
__global__ __launch_bounds__(256) void k_u(const float* __restrict__ enc) {
    __shared__ float a[112];
    int b = blockIdx.x;
    int h = b >> 4;
    int jc = (b >> 2) & 3;
    int ec = b & 3;
    int tid = threadIdx.x;
    const float* csr = g_s.cs + h * TKN;
    float mxl = -1e30f;
    for (int e = tid; e < ENCN; e += 256) mxl = fmaxf(mxl, csr[e]);
    float mx = blk_reduce(mxl, true);
    float sl = 0.f;
    for (int e = tid; e < ENCN; e += 256) sl += expf(csr[e] - mx);
    float S = blk_reduce(sl, false);
    float inv = 1.f / S;
    int e0 = ec * 110;
    int e1 = (e0 + 110 < ENCN) ? (e0 + 110) : ENCN;
    int ne = e1 - e0;
    if (tid < ne) a[tid] = expf(csr[e0 + tid] - mx) * inv;
    __syncthreads();
    int j = jc * 256 + tid;
    float acc = 0.f;
#pragma unroll 4
    for (int e = 0; e < ne; e++)
        acc = fmaf(a[e], __ldg(enc + (size_t)(e0 + e) * DD + j), acc);
    atomicAdd(&g_s.u[h * DD + j], acc);
}

// FFN second matmul with gelu(tanh); grid 256 = otile(8) x isplit(32)
__global__ __launch_bounds__(256) void k_ffn2(const float* __restrict__ w2, int l) {
    __shared__ float xs[128];
    int otile = blockIdx.x >> 5;
    int isplit = blockIdx.x & 31;
    int ibase = isplit * 128;
    if (threadIdx.x < 128) {
        float v = g_s.ffnpre[ibase + threadIdx.x];
        float v3 = v * v * v;
        xs[threadIdx.x] = 0.5f * v * (1.f + tanhf(0.7978845608028654f * (v + 0.044715f * v3)));
    }
    __syncthreads();
    gemv_core(w2 + (size_t)l * FF * DD, DD, xs, ibase, 128, otile * 128, g_s.x);
}

// final LN (redundant per block) + logits[v] = xf . emb[v,:]
__global__ __launch_bounds__(256) void k_logits(const float* __restrict__ emb,
                                                const float* __restrict__ lg,
                                                const float* __restrict__ lb,
                                                float* __restrict__ out) {
    __shared__ float xf[DD];
    blk_layernorm(g_s.x, lg, lb, xf);
    int w = threadIdx.x >> 5, ln = threadIdx.x & 31;
    int vb = (blockIdx.x * 8 + w) * 4;
    float4 xr[8];
#pragma unroll
    for (int kk = 0; kk < 8; kk++)
        xr[kk] = ((const float4*)xf)[kk * 32 + ln];
#pragma unroll
    for (int r = 0; r < 4; r++) {
        const float4* er = (const float4*)(emb + (size_t)(vb + r) * DD);
        float acc = 0.f;
#pragma unroll
        for (int kk = 0; kk < 8; kk++) {
            float4 e4 = __ldg(er + kk * 32 + ln);
            float4 x4 = xr[kk];
            acc += e4.x * x4.x + e4.y * x4.y + e4.z * x4.z + e4.w * x4.w;
        }
        acc = warp_sum(acc);
        if (ln == 0) out[vb + r] = acc;
    }
}

// ---------------- launcher ----------------
extern "C" void kernel_launch(void* const* d_in, const int* in_sizes, int n_in,
                              void* d_out, int out_size) {
    const int*   input_ids = (const int*)d_in[0];
    const float* enc    = (const float*)d_in[1];
    const float* past_k = (const float*)d_in[2];
    const float* past_v = (const float*)d_in[3];
    const float* emb    = (const float*)d_in[4];
    const float* pos    = (const float*)d_in[5];
    const float* ln1_g  = (const float*)d_in[6];
    const float* ln1_b  = (const float*)d_in[7];
    const float* wq_s   = (const float*)d_in[8];
    const float* wk_s   = (const float*)d_in[9];
    const float* wv_s   = (const float*)d_in[10];
    const float* wo_s   = (const float*)d_in[11];
    const float* ln2_g  = (const float*)d_in[12];
    const float* ln2_b  = (const float*)d_in[13];
    const float* wq_c   = (const float*)d_in[14];
    const float* wk_c   = (const float*)d_in[15];
    const float* wv_c   = (const float*)d_in[16];
    const float* wo_c   = (const float*)d_in[17];
    const float* ln3_g  = (const float*)d_in[18];
    const float* ln3_b  = (const float*)d_in[19];
    const float* w1     = (const float*)d_in[20];
    const float* w2     = (const float*)d_in[21];
    const float* lnf_g  = (const float*)d_in[22];
    const float* lnf_b  = (const float*)d_in[23];
    const int*   plen   = (const int*)d_in[24];
    float* out = (float*)d_out;

    void* sp = nullptr;
    cudaGetSymbolAddress(&sp, g_s);

    k_init<<<1, 256>>>(input_ids, plen, emb, pos);
    for (int l = 0; l < LL; l++) {
        cudaMemsetAsync(sp, 0, ZERO_FLOATS * sizeof(float));
        k_qkv<<<384, 256>>>(wq_s, wk_s, wv_s, ln1_g, ln1_b, l);
        k_sscore<<<448, 256>>>(past_k, l);
        k_sav<<<224, 128>>>(past_v, l);
        k_gemv_plain<<<256, 256>>>(wo_s, 0, l);            // x += o_s @ wo_s
        k_ln_gemv<<<128, 256>>>(wq_c, ln2_g, ln2_b, DD, 16, 0, l);  // qc
        k_t<<<128, 256>>>(wk_c, l);
        k_cscore<<<438, 256>>>(enc);
        k_u<<<128, 256>>>(enc);
        k_gemv_plain<<<256, 256>>>(wv_c, 2, l);            // oc = u @ wv_c (per-head)
        k_gemv_plain<<<256, 256>>>(wo_c, 1, l);            // x += o_c @ wo_c
        k_ln_gemv<<<256, 256>>>(w1, ln3_g, ln3_b, FF, 8, 1, l);     // ffnpre
        k_ffn2<<<256, 256>>>(w2, l);                        // x += gelu(ffnpre) @ w2
    }
    k_logits<<<512, 256>>>(emb, lnf_g, lnf_b, out);
}